// round 14
// baseline (speedup 1.0000x reference)
#include <cuda_runtime.h>
#include <cuda_fp16.h>
#include <cstdint>

#define NN   50000
#define NE   800000
#define FIN  128
#define FHID 384
#define FOUT 256
#define NB   196          // ceil(NN/256) scan blocks

// ----------------------------- scratch --------------------------------------
__device__ __half g_agg1h[NN * FIN];             // 12.8 MB
__device__ __half g_x1h[(size_t)NN * FHID];      // 38.4 MB
__device__ __half g_y_h[(size_t)NN * FOUT];      // 25.6 MB
__device__ __half g_feat_h[NN * FIN];            // 12.8 MB (features * out_norm)
__device__ __half g_w1t[FHID * FIN];             // W1^T fp16 [384][128]
__device__ __half g_w2t[FOUT * FHID];            // W2^T fp16 [256][384]
__device__ int    g_deg[2 * NN];
__device__ float  g_out_norm[NN];
__device__ float  g_in_norm[NN];
__device__ int    g_off[NN + 1];
__device__ int    g_cursor[NN];
__device__ int    g_csr_src[NE];
__device__ int    g_incl[NN];
__device__ int    g_bsum[256];

// ----------------------------- helpers --------------------------------------
__device__ __forceinline__ void ldsm_x4(unsigned& r0, unsigned& r1,
                                        unsigned& r2, unsigned& r3, unsigned addr) {
    asm volatile("ldmatrix.sync.aligned.m8n8.x4.shared.b16 {%0,%1,%2,%3}, [%4];"
                 : "=r"(r0), "=r"(r1), "=r"(r2), "=r"(r3) : "r"(addr));
}

__device__ __forceinline__ void mma_f16(float& c0, float& c1, float& c2, float& c3,
                                        unsigned a0, unsigned a1, unsigned a2, unsigned a3,
                                        unsigned b0, unsigned b1) {
    asm volatile("mma.sync.aligned.m16n8k16.row.col.f32.f16.f16.f32 "
                 "{%0,%1,%2,%3}, {%4,%5,%6,%7}, {%8,%9}, {%0,%1,%2,%3};"
                 : "+f"(c0), "+f"(c1), "+f"(c2), "+f"(c3)
                 : "r"(a0), "r"(a1), "r"(a2), "r"(a3), "r"(b0), "r"(b1));
}

__device__ __forceinline__ void cp16(unsigned dst, const void* src, int src_sz) {
    asm volatile("cp.async.cg.shared.global [%0], [%1], 16, %2;"
                 :: "r"(dst), "l"(src), "r"(src_sz));
}
__device__ __forceinline__ void cp_commit() { asm volatile("cp.async.commit_group;"); }
template<int N_>
__device__ __forceinline__ void cp_wait() {
    asm volatile("cp.async.wait_group %0;" :: "n"(N_));
}
__device__ __forceinline__ __half2 bits2h(unsigned u) {
    return *reinterpret_cast<__half2*>(&u);
}

// ----------------------------- prelude kernels -------------------------------
// Both weight transposes in one launch. W1: 12x4 tiles (48 blocks), W2: 8x12 (96).
__global__ void wtrans2_kernel(const float* __restrict__ W1, __half* __restrict__ W1t,
                               const float* __restrict__ W2, __half* __restrict__ W2t) {
    __shared__ float tile[32][33];
    const float* W; __half* Wt; int R, C, bx, by;
    int b = blockIdx.x;
    if (b < 48) {             // W1: R=FIN rows, C=FHID cols; tiles 12 x 4
        W = W1; Wt = W1t; R = FIN; C = FHID;
        bx = (b % 12) * 32; by = (b / 12) * 32;
    } else {                  // W2: R=FHID, C=FOUT; tiles 8 x 12
        b -= 48;
        W = W2; Wt = W2t; R = FHID; C = FOUT;
        bx = (b % 8) * 32; by = (b / 8) * 32;
    }
    int x = bx + threadIdx.x;
#pragma unroll
    for (int i = 0; i < 32; i += 8) {
        int y = by + threadIdx.y + i;
        if (y < R && x < C) tile[threadIdx.y + i][threadIdx.x] = W[(size_t)y * C + x];
    }
    __syncthreads();
    int k = by + threadIdx.x;
#pragma unroll
    for (int i = 0; i < 32; i += 8) {
        int n = bx + threadIdx.y + i;
        if (n < C && k < R)
            Wt[(size_t)n * R + k] = __float2half(tile[threadIdx.x][threadIdx.y + i]);
    }
}

__global__ void degree_kernel(const int* __restrict__ ei, int* __restrict__ deg) {
    int q = blockIdx.x * blockDim.x + threadIdx.x;
    if (q < NE / 4) {
        int4 s = ((const int4*)ei)[q];
        int4 d = ((const int4*)(ei + NE))[q];
        atomicAdd(&deg[s.x], 1); atomicAdd(&deg[s.y], 1);
        atomicAdd(&deg[s.z], 1); atomicAdd(&deg[s.w], 1);
        atomicAdd(&deg[NN + d.x], 1); atomicAdd(&deg[NN + d.y], 1);
        atomicAdd(&deg[NN + d.z], 1); atomicAdd(&deg[NN + d.w], 1);
    }
}

__global__ void scan1_kernel(const int* __restrict__ deg,
                             int* __restrict__ incl, int* __restrict__ bsum) {
    __shared__ int sh[256];
    int t = threadIdx.x;
    int i = blockIdx.x * 256 + t;
    int v = (i < NN) ? deg[NN + i] : 0;
    sh[t] = v;
    __syncthreads();
#pragma unroll
    for (int d = 1; d < 256; d <<= 1) {
        int x = (t >= d) ? sh[t - d] : 0;
        __syncthreads();
        if (t >= d) sh[t] += x;
        __syncthreads();
    }
    if (i < NN) incl[i] = sh[t];
    if (t == 255) bsum[blockIdx.x] = sh[255];
}

__global__ void scan3_kernel(const int* __restrict__ deg,
                             const int* __restrict__ incl, const int* __restrict__ bsum,
                             int* __restrict__ off, int* __restrict__ cursor,
                             float* __restrict__ onorm, float* __restrict__ inorm) {
    __shared__ int sh[256];
    int t = threadIdx.x;
    sh[t] = (t < blockIdx.x && t < NB) ? bsum[t] : 0;
    __syncthreads();
#pragma unroll
    for (int d = 128; d > 0; d >>= 1) {
        if (t < d) sh[t] += sh[t + d];
        __syncthreads();
    }
    int bpre = sh[0];
    int i = blockIdx.x * 256 + t;
    if (i < NN) {
        int din = deg[NN + i];
        int excl = bpre + incl[i] - din;
        off[i] = excl;
        cursor[i] = excl;
        onorm[i] = rsqrtf((float)max(deg[i], 1));
        inorm[i] = rsqrtf((float)max(din, 1));
    }
    if (i == 0) off[NN] = NE;
}

__global__ void scatter_f2h_kernel(const int* __restrict__ ei,
                                   int* __restrict__ cursor,
                                   int* __restrict__ csr_src,
                                   const float* __restrict__ feat,
                                   const float* __restrict__ onorm,
                                   __half* __restrict__ feat_h) {
    int q = blockIdx.x * blockDim.x + threadIdx.x;
    if (q < NE / 4) {
        int4 s = ((const int4*)ei)[q];
        int4 d = ((const int4*)(ei + NE))[q];
        csr_src[atomicAdd(&cursor[d.x], 1)] = s.x;
        csr_src[atomicAdd(&cursor[d.y], 1)] = s.y;
        csr_src[atomicAdd(&cursor[d.z], 1)] = s.z;
        csr_src[atomicAdd(&cursor[d.w], 1)] = s.w;
    }
    const int n4 = NN * (FIN / 4);
    int total = blockDim.x * gridDim.x;
    for (int i = q; i < n4; i += total) {
        int row = i >> 5;
        float sc = __ldg(&onorm[row]);
        float4 v = ((const float4*)feat)[i];
        __half2 h0 = __floats2half2_rn(v.x * sc, v.y * sc);
        __half2 h1 = __floats2half2_rn(v.z * sc, v.w * sc);
        ((uint2*)feat_h)[i] = make_uint2(*(unsigned*)&h0, *(unsigned*)&h1);
    }
}

// ----------------------------- gathers (MLP x8) -------------------------------
// 8 neighbor loads in flight; reduction stays per-4 fp16 tree + fp32 flush
// (precision identical to the MLP x4 version).

__global__ void agg1_gather_kernel(const int* __restrict__ off,
                                   const int* __restrict__ csr_src,
                                   const __half* __restrict__ feat,
                                   __half* __restrict__ aggh) {
    int n = (blockIdx.x * blockDim.x + threadIdx.x) >> 5;
    if (n >= NN) return;
    int lane = threadIdx.x & 31;
    int beg = off[n], end = off[n + 1];
    float4 acc = make_float4(0.f, 0.f, 0.f, 0.f);
    for (int j = beg; j < end; j += 32) {
        int m = min(32, end - j);
        int s = (lane < m) ? __ldg(&csr_src[j + lane]) : 0;
        int k = 0;
        for (; k + 8 <= m; k += 8) {
            uint2 u[8];
#pragma unroll
            for (int e = 0; e < 8; e++) {
                int se = __shfl_sync(0xffffffffu, s, k + e);
                u[e] = __ldg((const uint2*)(feat + (size_t)se * FIN + lane * 4));
            }
#pragma unroll
            for (int g = 0; g < 2; g++) {
                __half2 ax = __hadd2(__hadd2(bits2h(u[4*g+0].x), bits2h(u[4*g+1].x)),
                                     __hadd2(bits2h(u[4*g+2].x), bits2h(u[4*g+3].x)));
                __half2 ay = __hadd2(__hadd2(bits2h(u[4*g+0].y), bits2h(u[4*g+1].y)),
                                     __hadd2(bits2h(u[4*g+2].y), bits2h(u[4*g+3].y)));
                float2 f0 = __half22float2(ax);
                float2 f1 = __half22float2(ay);
                acc.x += f0.x; acc.y += f0.y; acc.z += f1.x; acc.w += f1.y;
            }
        }
        for (; k + 4 <= m; k += 4) {
            uint2 u[4];
#pragma unroll
            for (int e = 0; e < 4; e++) {
                int se = __shfl_sync(0xffffffffu, s, k + e);
                u[e] = __ldg((const uint2*)(feat + (size_t)se * FIN + lane * 4));
            }
            __half2 ax = __hadd2(__hadd2(bits2h(u[0].x), bits2h(u[1].x)),
                                 __hadd2(bits2h(u[2].x), bits2h(u[3].x)));
            __half2 ay = __hadd2(__hadd2(bits2h(u[0].y), bits2h(u[1].y)),
                                 __hadd2(bits2h(u[2].y), bits2h(u[3].y)));
            float2 f0 = __half22float2(ax);
            float2 f1 = __half22float2(ay);
            acc.x += f0.x; acc.y += f0.y; acc.z += f1.x; acc.w += f1.y;
        }
        for (; k < m; k++) {
            int ss = __shfl_sync(0xffffffffu, s, k);
            uint2 u = __ldg((const uint2*)(feat + (size_t)ss * FIN + lane * 4));
            float2 a = __half22float2(bits2h(u.x));
            float2 b = __half22float2(bits2h(u.y));
            acc.x += a.x; acc.y += a.y; acc.z += b.x; acc.w += b.y;
        }
    }
    __half2 h0 = __floats2half2_rn(acc.x, acc.y);
    __half2 h1 = __floats2half2_rn(acc.z, acc.w);
    ((uint2*)(aggh + (size_t)n * FIN))[lane] = make_uint2(*(unsigned*)&h0, *(unsigned*)&h1);
}

// 2 warps per node: warp-half h owns columns [h*128, (h+1)*128), lane*4 halves.
__global__ void agg2_gather_kernel(const int* __restrict__ off,
                                   const int* __restrict__ csr_src,
                                   const __half* __restrict__ y,
                                   const float* __restrict__ inorm,
                                   const float* __restrict__ b2,
                                   float* __restrict__ out) {
    int gid = blockIdx.x * blockDim.x + threadIdx.x;
    int n = gid >> 6;
    if (n >= NN) return;
    int half = (gid >> 5) & 1;
    int lane = threadIdx.x & 31;
    int cbase = half * 128 + lane * 4;
    int beg = off[n], end = off[n + 1];
    float acc[4] = {0.f, 0.f, 0.f, 0.f};
    for (int j = beg; j < end; j += 32) {
        int m = min(32, end - j);
        int s = (lane < m) ? __ldg(&csr_src[j + lane]) : 0;
        int k = 0;
        for (; k + 8 <= m; k += 8) {
            uint2 u[8];
#pragma unroll
            for (int e = 0; e < 8; e++) {
                int se = __shfl_sync(0xffffffffu, s, k + e);
                u[e] = __ldg((const uint2*)(y + (size_t)se * FOUT + cbase));
            }
#pragma unroll
            for (int g = 0; g < 2; g++) {
                __half2 ax = __hadd2(__hadd2(bits2h(u[4*g+0].x), bits2h(u[4*g+1].x)),
                                     __hadd2(bits2h(u[4*g+2].x), bits2h(u[4*g+3].x)));
                __half2 ay = __hadd2(__hadd2(bits2h(u[4*g+0].y), bits2h(u[4*g+1].y)),
                                     __hadd2(bits2h(u[4*g+2].y), bits2h(u[4*g+3].y)));
                float2 f0 = __half22float2(ax);
                float2 f1 = __half22float2(ay);
                acc[0] += f0.x; acc[1] += f0.y; acc[2] += f1.x; acc[3] += f1.y;
            }
        }
        for (; k + 4 <= m; k += 4) {
            uint2 u[4];
#pragma unroll
            for (int e = 0; e < 4; e++) {
                int se = __shfl_sync(0xffffffffu, s, k + e);
                u[e] = __ldg((const uint2*)(y + (size_t)se * FOUT + cbase));
            }
            __half2 ax = __hadd2(__hadd2(bits2h(u[0].x), bits2h(u[1].x)),
                                 __hadd2(bits2h(u[2].x), bits2h(u[3].x)));
            __half2 ay = __hadd2(__hadd2(bits2h(u[0].y), bits2h(u[1].y)),
                                 __hadd2(bits2h(u[2].y), bits2h(u[3].y)));
            float2 f0 = __half22float2(ax);
            float2 f1 = __half22float2(ay);
            acc[0] += f0.x; acc[1] += f0.y; acc[2] += f1.x; acc[3] += f1.y;
        }
        for (; k < m; k++) {
            int ss = __shfl_sync(0xffffffffu, s, k);
            uint2 u = __ldg((const uint2*)(y + (size_t)ss * FOUT + cbase));
            float2 f0 = __half22float2(bits2h(u.x));
            float2 f1 = __half22float2(bits2h(u.y));
            acc[0] += f0.x; acc[1] += f0.y; acc[2] += f1.x; acc[3] += f1.y;
        }
    }
    float sc = __ldg(&inorm[n]);
    float4 bb = *(const float4*)(b2 + cbase);
    float4 o;
    o.x = acc[0] * sc + bb.x;
    o.y = acc[1] * sc + bb.y;
    o.z = acc[2] * sc + bb.z;
    o.w = acc[3] * sc + bb.w;
    *(float4*)(out + (size_t)n * FOUT + cbase) = o;
}

// ----------------------------- fp16 tensor GEMM (cp.async, BM=128 BN=128 BK=64)
// (round-13 version; GEMMs are pipe-bound at the legacy-HMMA ceiling)
#define ROWH 72
#define GEMM_SMEM ((2 * 128 * ROWH + 2 * 128 * ROWH) * 2)   // 72 KB

template<bool RELU, bool HAS_BIAS>
__global__ __launch_bounds__(256)
void gemm_f16_kernel(const __half* __restrict__ A, const __half* __restrict__ Bt,
                     __half* __restrict__ C,
                     const float* __restrict__ rowscale,
                     const float* __restrict__ bias,
                     int M, int N, int K) {
    constexpr int BK = 64;
    extern __shared__ __align__(16) __half dynsmem[];
    __half* As = dynsmem;
    __half* Bs = dynsmem + 2 * 128 * ROWH;

    const int tid  = threadIdx.x;
    const int warp = tid >> 5;
    const int lane = tid & 31;
    const int wm = warp & 3;
    const int wn = warp >> 2;
    const int quad = lane >> 3;
    const int qr   = lane & 7;

    const int brow0 = blockIdx.y * 128;
    const int bcol0 = blockIdx.x * 128;

    const int st_c8 = tid & 7;
    const int st_r  = tid >> 3;

    unsigned as_base = (unsigned)__cvta_generic_to_shared(As);
    unsigned bs_base = (unsigned)__cvta_generic_to_shared(Bs);

    unsigned a_off[2], b_off[4];
#pragma unroll
    for (int mt = 0; mt < 2; mt++) {
        int row = wm * 32 + mt * 16 + qr + (quad & 1) * 8;
        a_off[mt] = (unsigned)((row * ROWH + (quad >> 1) * 8) * 2);
    }
#pragma unroll
    for (int ntp = 0; ntp < 4; ntp++) {
        int row = wn * 64 + ntp * 16 + (quad >> 1) * 8 + qr;
        b_off[ntp] = (unsigned)((row * ROWH + (quad & 1) * 8) * 2);
    }

    float acc[2][8][4];
#pragma unroll
    for (int mt = 0; mt < 2; mt++)
#pragma unroll
        for (int nt = 0; nt < 8; nt++)
#pragma unroll
            for (int f = 0; f < 4; f++) acc[mt][nt][f] = 0.f;

    auto stage = [&](int k0, int buf) {
#pragma unroll
        for (int l = 0; l < 4; l++) {
            int row = st_r + l * 32;
            int grow = brow0 + row;
            unsigned dst = as_base + (unsigned)((buf * 128 * ROWH + row * ROWH + st_c8 * 8) * 2);
            const __half* src = A + (size_t)grow * K + k0 + st_c8 * 8;
            cp16(dst, src, (grow < M) ? 16 : 0);
        }
#pragma unroll
        for (int l = 0; l < 4; l++) {
            int row = st_r + l * 32;
            unsigned dst = bs_base + (unsigned)((buf * 128 * ROWH + row * ROWH + st_c8 * 8) * 2);
            const __half* src = Bt + (size_t)(bcol0 + row) * K + k0 + st_c8 * 8;
            cp16(dst, src, 16);
        }
        cp_commit();
    };

    stage(0, 0);
    int buf = 0;
    const int KT = K / BK;

    for (int kt = 0; kt < KT; kt++) {
        if (kt + 1 < KT) {
            stage((kt + 1) * BK, buf ^ 1);
            cp_wait<1>();
        } else {
            cp_wait<0>();
        }
        __syncthreads();

        unsigned abuf = as_base + (unsigned)(buf * 128 * ROWH * 2);
        unsigned bbuf = bs_base + (unsigned)(buf * 128 * ROWH * 2);
#pragma unroll
        for (int ks = 0; ks < 4; ks++) {
            unsigned a[2][4], b[4][4];
#pragma unroll
            for (int mt = 0; mt < 2; mt++)
                ldsm_x4(a[mt][0], a[mt][1], a[mt][2], a[mt][3],
                        abuf + a_off[mt] + ks * 32);
#pragma unroll
            for (int ntp = 0; ntp < 4; ntp++)
                ldsm_x4(b[ntp][0], b[ntp][1], b[ntp][2], b[ntp][3],
                        bbuf + b_off[ntp] + ks * 32);
#pragma unroll
            for (int mt = 0; mt < 2; mt++)
#pragma unroll
                for (int nt = 0; nt < 8; nt++) {
                    unsigned b0 = b[nt >> 1][(nt & 1) * 2 + 0];
                    unsigned b1 = b[nt >> 1][(nt & 1) * 2 + 1];
                    mma_f16(acc[mt][nt][0], acc[mt][nt][1],
                            acc[mt][nt][2], acc[mt][nt][3],
                            a[mt][0], a[mt][1], a[mt][2], a[mt][3], b0, b1);
                }
        }
        __syncthreads();
        buf ^= 1;
    }

    const int gid = lane >> 2;
    const int tig = lane & 3;
#pragma unroll
    for (int mt = 0; mt < 2; mt++) {
        int r0 = brow0 + wm * 32 + mt * 16 + gid;
        int r1 = r0 + 8;
        float rs0 = (r0 < M) ? __ldg(&rowscale[r0]) : 0.f;
        float rs1 = (r1 < M) ? __ldg(&rowscale[r1]) : 0.f;
#pragma unroll
        for (int nt = 0; nt < 8; nt++) {
            int c = bcol0 + wn * 64 + nt * 8 + 2 * tig;
            float2 bb = make_float2(0.f, 0.f);
            if (HAS_BIAS) bb = *(const float2*)(bias + c);
            float2 o0, o1;
            o0.x = acc[mt][nt][0] * rs0 + bb.x;
            o0.y = acc[mt][nt][1] * rs0 + bb.y;
            o1.x = acc[mt][nt][2] * rs1 + bb.x;
            o1.y = acc[mt][nt][3] * rs1 + bb.y;
            if (RELU) {
                o0.x = fmaxf(o0.x, 0.f); o0.y = fmaxf(o0.y, 0.f);
                o1.x = fmaxf(o1.x, 0.f); o1.y = fmaxf(o1.y, 0.f);
            }
            if (r0 < M) *(__half2*)(C + (size_t)r0 * N + c) = __floats2half2_rn(o0.x, o0.y);
            if (r1 < M) *(__half2*)(C + (size_t)r1 * N + c) = __floats2half2_rn(o1.x, o1.y);
        }
    }
}

// ----------------------------- launch ---------------------------------------
extern "C" void kernel_launch(void* const* d_in, const int* in_sizes, int n_in,
                              void* d_out, int out_size) {
    const float *features = nullptr, *W1 = nullptr, *b1 = nullptr,
                *W2 = nullptr, *b2 = nullptr;
    const int* ei = nullptr;
    for (int i = 0; i < n_in; i++) {
        switch (in_sizes[i]) {
            case NN * FIN:      features = (const float*)d_in[i]; break;
            case FIN * FHID:    W1 = (const float*)d_in[i]; break;
            case FHID:          b1 = (const float*)d_in[i]; break;
            case FHID * FOUT:   W2 = (const float*)d_in[i]; break;
            case FOUT:          b2 = (const float*)d_in[i]; break;
            case 2 * NE:        ei = (const int*)d_in[i]; break;
            default: break;
        }
    }
    float* out = (float*)d_out;

    float *onorm, *inorm;
    __half *agg1h, *x1h, *y_h, *feat_h, *w1t, *w2t;
    int *deg, *off, *cursor, *csr_src, *incl, *bsum;
    cudaGetSymbolAddress((void**)&agg1h,   g_agg1h);
    cudaGetSymbolAddress((void**)&x1h,     g_x1h);
    cudaGetSymbolAddress((void**)&y_h,     g_y_h);
    cudaGetSymbolAddress((void**)&feat_h,  g_feat_h);
    cudaGetSymbolAddress((void**)&w1t,     g_w1t);
    cudaGetSymbolAddress((void**)&w2t,     g_w2t);
    cudaGetSymbolAddress((void**)&onorm,   g_out_norm);
    cudaGetSymbolAddress((void**)&inorm,   g_in_norm);
    cudaGetSymbolAddress((void**)&deg,     g_deg);
    cudaGetSymbolAddress((void**)&off,     g_off);
    cudaGetSymbolAddress((void**)&cursor,  g_cursor);
    cudaGetSymbolAddress((void**)&csr_src, g_csr_src);
    cudaGetSymbolAddress((void**)&incl,    g_incl);
    cudaGetSymbolAddress((void**)&bsum,    g_bsum);

    cudaFuncSetAttribute(gemm_f16_kernel<true, true>,
                         cudaFuncAttributeMaxDynamicSharedMemorySize, GEMM_SMEM);
    cudaFuncSetAttribute(gemm_f16_kernel<false, false>,
                         cudaFuncAttributeMaxDynamicSharedMemorySize, GEMM_SMEM);

    const int T = 256;

    cudaMemsetAsync(deg, 0, 2 * NN * sizeof(int));
    wtrans2_kernel<<<144, dim3(32, 8)>>>(W1, w1t, W2, w2t);
    degree_kernel<<<(NE / 4 + T - 1) / T, T>>>(ei, deg);
    scan1_kernel<<<NB, 256>>>(deg, incl, bsum);
    scan3_kernel<<<NB, 256>>>(deg, incl, bsum, off, cursor, onorm, inorm);
    scatter_f2h_kernel<<<(NE / 4 + T - 1) / T, T>>>(ei, cursor, csr_src,
                                                    features, onorm, feat_h);
    {
        long long threads = (long long)NN * 32;
        agg1_gather_kernel<<<(unsigned)((threads + T - 1) / T), T>>>(
            off, csr_src, feat_h, agg1h);
    }
    {
        dim3 grid(FHID / 128, (NN + 127) / 128);
        gemm_f16_kernel<true, true><<<grid, 256, GEMM_SMEM>>>(
            agg1h, w1t, x1h, inorm, b1, NN, FHID, FIN);
    }
    {
        dim3 grid(FOUT / 128, (NN + 127) / 128);
        gemm_f16_kernel<false, false><<<grid, 256, GEMM_SMEM>>>(
            x1h, w2t, y_h, onorm, nullptr, NN, FOUT, FHID);
    }
    {
        long long threads = (long long)NN * 64;   // 2 warps per node
        agg2_gather_kernel<<<(unsigned)((threads + T - 1) / T), T>>>(
            off, csr_src, y_h, inorm, b2, out);
    }
}

// round 15
// speedup vs baseline: 1.0783x; 1.0783x over previous
#include <cuda_runtime.h>
#include <cuda_fp16.h>
#include <cstdint>

#define NN   50000
#define NE   800000
#define FIN  128
#define FHID 384
#define FOUT 256
#define NB   196          // ceil(NN/256) scan blocks

// ----------------------------- scratch --------------------------------------
__device__ __half g_agg1h[NN * FIN];             // 12.8 MB
__device__ __half g_x1h[(size_t)NN * FHID];      // 38.4 MB
__device__ __half g_y_h[(size_t)NN * FOUT];      // 25.6 MB
__device__ __half g_feat_h[NN * FIN];            // 12.8 MB (features * out_norm)
__device__ __half g_w1t[FHID * FIN];             // W1^T fp16 [384][128]
__device__ __half g_w2t[FOUT * FHID];            // W2^T fp16 [256][384]
__device__ int    g_deg[2 * NN];
__device__ float  g_out_norm[NN];
__device__ float  g_in_norm[NN];
__device__ int    g_off[NN + 1];
__device__ int    g_cursor[NN];
__device__ int    g_csr_src[NE];
__device__ int    g_incl[NN];
__device__ int    g_bsum[256];

// ----------------------------- helpers --------------------------------------
__device__ __forceinline__ void ldsm_x4(unsigned& r0, unsigned& r1,
                                        unsigned& r2, unsigned& r3, unsigned addr) {
    asm volatile("ldmatrix.sync.aligned.m8n8.x4.shared.b16 {%0,%1,%2,%3}, [%4];"
                 : "=r"(r0), "=r"(r1), "=r"(r2), "=r"(r3) : "r"(addr));
}

__device__ __forceinline__ void mma_f16(float& c0, float& c1, float& c2, float& c3,
                                        unsigned a0, unsigned a1, unsigned a2, unsigned a3,
                                        unsigned b0, unsigned b1) {
    asm volatile("mma.sync.aligned.m16n8k16.row.col.f32.f16.f16.f32 "
                 "{%0,%1,%2,%3}, {%4,%5,%6,%7}, {%8,%9}, {%0,%1,%2,%3};"
                 : "+f"(c0), "+f"(c1), "+f"(c2), "+f"(c3)
                 : "r"(a0), "r"(a1), "r"(a2), "r"(a3), "r"(b0), "r"(b1));
}

__device__ __forceinline__ void cp16(unsigned dst, const void* src, int src_sz) {
    asm volatile("cp.async.cg.shared.global [%0], [%1], 16, %2;"
                 :: "r"(dst), "l"(src), "r"(src_sz));
}
__device__ __forceinline__ void cp_commit() { asm volatile("cp.async.commit_group;"); }
template<int N_>
__device__ __forceinline__ void cp_wait() {
    asm volatile("cp.async.wait_group %0;" :: "n"(N_));
}
__device__ __forceinline__ __half2 bits2h(unsigned u) {
    return *reinterpret_cast<__half2*>(&u);
}

// ----------------------------- prelude kernels -------------------------------
// Fused: blocks 0-143 transpose W1/W2 to fp16; blocks 144+ count degrees
// (independent work; one launch instead of two).
#define WT_BLOCKS 144
__global__ void wtrans_degree_kernel(const float* __restrict__ W1, __half* __restrict__ W1t,
                                     const float* __restrict__ W2, __half* __restrict__ W2t,
                                     const int* __restrict__ ei, int* __restrict__ deg) {
    int b = blockIdx.x;
    if (b < WT_BLOCKS) {
        // ---- weight transpose path (256 threads as 32x8)
        __shared__ float tile[32][33];
        const float* W; __half* Wt; int R, C, bx, by;
        if (b < 48) {         // W1: R=FIN, C=FHID; tiles 12 x 4
            W = W1; Wt = W1t; R = FIN; C = FHID;
            bx = (b % 12) * 32; by = (b / 12) * 32;
        } else {              // W2: R=FHID, C=FOUT; tiles 8 x 12
            int bb = b - 48;
            W = W2; Wt = W2t; R = FHID; C = FOUT;
            bx = (bb % 8) * 32; by = (bb / 8) * 32;
        }
        int tx = threadIdx.x & 31;
        int ty = threadIdx.x >> 5;     // 0..7
        int x = bx + tx;
#pragma unroll
        for (int i = 0; i < 32; i += 8) {
            int y = by + ty + i;
            if (y < R && x < C) tile[ty + i][tx] = W[(size_t)y * C + x];
        }
        __syncthreads();
        int k = by + tx;
#pragma unroll
        for (int i = 0; i < 32; i += 8) {
            int n = bx + ty + i;
            if (n < C && k < R)
                Wt[(size_t)n * R + k] = __float2half(tile[tx][ty + i]);
        }
    } else {
        // ---- degree path: 4 edges per thread via int4
        int q = (b - WT_BLOCKS) * blockDim.x + threadIdx.x;
        if (q < NE / 4) {
            int4 s = ((const int4*)ei)[q];
            int4 d = ((const int4*)(ei + NE))[q];
            atomicAdd(&deg[s.x], 1); atomicAdd(&deg[s.y], 1);
            atomicAdd(&deg[s.z], 1); atomicAdd(&deg[s.w], 1);
            atomicAdd(&deg[NN + d.x], 1); atomicAdd(&deg[NN + d.y], 1);
            atomicAdd(&deg[NN + d.z], 1); atomicAdd(&deg[NN + d.w], 1);
        }
    }
}

__global__ void scan1_kernel(const int* __restrict__ deg,
                             int* __restrict__ incl, int* __restrict__ bsum) {
    __shared__ int sh[256];
    int t = threadIdx.x;
    int i = blockIdx.x * 256 + t;
    int v = (i < NN) ? deg[NN + i] : 0;
    sh[t] = v;
    __syncthreads();
#pragma unroll
    for (int d = 1; d < 256; d <<= 1) {
        int x = (t >= d) ? sh[t - d] : 0;
        __syncthreads();
        if (t >= d) sh[t] += x;
        __syncthreads();
    }
    if (i < NN) incl[i] = sh[t];
    if (t == 255) bsum[blockIdx.x] = sh[255];
}

__global__ void scan3_kernel(const int* __restrict__ deg,
                             const int* __restrict__ incl, const int* __restrict__ bsum,
                             int* __restrict__ off, int* __restrict__ cursor,
                             float* __restrict__ onorm, float* __restrict__ inorm) {
    __shared__ int sh[256];
    int t = threadIdx.x;
    sh[t] = (t < blockIdx.x && t < NB) ? bsum[t] : 0;
    __syncthreads();
#pragma unroll
    for (int d = 128; d > 0; d >>= 1) {
        if (t < d) sh[t] += sh[t + d];
        __syncthreads();
    }
    int bpre = sh[0];
    int i = blockIdx.x * 256 + t;
    if (i < NN) {
        int din = deg[NN + i];
        int excl = bpre + incl[i] - din;
        off[i] = excl;
        cursor[i] = excl;
        onorm[i] = rsqrtf((float)max(deg[i], 1));
        inorm[i] = rsqrtf((float)max(din, 1));
    }
    if (i == 0) off[NN] = NE;
}

__global__ void scatter_f2h_kernel(const int* __restrict__ ei,
                                   int* __restrict__ cursor,
                                   int* __restrict__ csr_src,
                                   const float* __restrict__ feat,
                                   const float* __restrict__ onorm,
                                   __half* __restrict__ feat_h) {
    int q = blockIdx.x * blockDim.x + threadIdx.x;
    if (q < NE / 4) {
        int4 s = ((const int4*)ei)[q];
        int4 d = ((const int4*)(ei + NE))[q];
        csr_src[atomicAdd(&cursor[d.x], 1)] = s.x;
        csr_src[atomicAdd(&cursor[d.y], 1)] = s.y;
        csr_src[atomicAdd(&cursor[d.z], 1)] = s.z;
        csr_src[atomicAdd(&cursor[d.w], 1)] = s.w;
    }
    const int n4 = NN * (FIN / 4);
    int total = blockDim.x * gridDim.x;
    for (int i = q; i < n4; i += total) {
        int row = i >> 5;
        float sc = __ldg(&onorm[row]);
        float4 v = ((const float4*)feat)[i];
        __half2 h0 = __floats2half2_rn(v.x * sc, v.y * sc);
        __half2 h1 = __floats2half2_rn(v.z * sc, v.w * sc);
        ((uint2*)feat_h)[i] = make_uint2(*(unsigned*)&h0, *(unsigned*)&h1);
    }
}

// ----------------------------- gathers (MLP x4, round-13 proven) -------------
__global__ void agg1_gather_kernel(const int* __restrict__ off,
                                   const int* __restrict__ csr_src,
                                   const __half* __restrict__ feat,
                                   __half* __restrict__ aggh) {
    int n = (blockIdx.x * blockDim.x + threadIdx.x) >> 5;
    if (n >= NN) return;
    int lane = threadIdx.x & 31;
    int beg = off[n], end = off[n + 1];
    float4 acc = make_float4(0.f, 0.f, 0.f, 0.f);
    for (int j = beg; j < end; j += 32) {
        int m = min(32, end - j);
        int s = (lane < m) ? __ldg(&csr_src[j + lane]) : 0;
        int k = 0;
        for (; k + 4 <= m; k += 4) {
            int s0 = __shfl_sync(0xffffffffu, s, k + 0);
            int s1 = __shfl_sync(0xffffffffu, s, k + 1);
            int s2 = __shfl_sync(0xffffffffu, s, k + 2);
            int s3 = __shfl_sync(0xffffffffu, s, k + 3);
            uint2 u0 = __ldg((const uint2*)(feat + (size_t)s0 * FIN + lane * 4));
            uint2 u1 = __ldg((const uint2*)(feat + (size_t)s1 * FIN + lane * 4));
            uint2 u2 = __ldg((const uint2*)(feat + (size_t)s2 * FIN + lane * 4));
            uint2 u3 = __ldg((const uint2*)(feat + (size_t)s3 * FIN + lane * 4));
            __half2 ax = __hadd2(__hadd2(bits2h(u0.x), bits2h(u1.x)),
                                 __hadd2(bits2h(u2.x), bits2h(u3.x)));
            __half2 ay = __hadd2(__hadd2(bits2h(u0.y), bits2h(u1.y)),
                                 __hadd2(bits2h(u2.y), bits2h(u3.y)));
            float2 f0 = __half22float2(ax);
            float2 f1 = __half22float2(ay);
            acc.x += f0.x; acc.y += f0.y; acc.z += f1.x; acc.w += f1.y;
        }
        for (; k < m; k++) {
            int ss = __shfl_sync(0xffffffffu, s, k);
            uint2 u = __ldg((const uint2*)(feat + (size_t)ss * FIN + lane * 4));
            float2 a = __half22float2(bits2h(u.x));
            float2 b = __half22float2(bits2h(u.y));
            acc.x += a.x; acc.y += a.y; acc.z += b.x; acc.w += b.y;
        }
    }
    __half2 h0 = __floats2half2_rn(acc.x, acc.y);
    __half2 h1 = __floats2half2_rn(acc.z, acc.w);
    ((uint2*)(aggh + (size_t)n * FIN))[lane] = make_uint2(*(unsigned*)&h0, *(unsigned*)&h1);
}

// 2 warps per node: warp-half h owns columns [h*128, (h+1)*128), lane*4 halves.
__global__ void agg2_gather_kernel(const int* __restrict__ off,
                                   const int* __restrict__ csr_src,
                                   const __half* __restrict__ y,
                                   const float* __restrict__ inorm,
                                   const float* __restrict__ b2,
                                   float* __restrict__ out) {
    int gid = blockIdx.x * blockDim.x + threadIdx.x;
    int n = gid >> 6;
    if (n >= NN) return;
    int half = (gid >> 5) & 1;
    int lane = threadIdx.x & 31;
    int cbase = half * 128 + lane * 4;
    int beg = off[n], end = off[n + 1];
    float acc[4] = {0.f, 0.f, 0.f, 0.f};
    for (int j = beg; j < end; j += 32) {
        int m = min(32, end - j);
        int s = (lane < m) ? __ldg(&csr_src[j + lane]) : 0;
        int k = 0;
        for (; k + 4 <= m; k += 4) {
            int s0 = __shfl_sync(0xffffffffu, s, k + 0);
            int s1 = __shfl_sync(0xffffffffu, s, k + 1);
            int s2 = __shfl_sync(0xffffffffu, s, k + 2);
            int s3 = __shfl_sync(0xffffffffu, s, k + 3);
            uint2 u0 = __ldg((const uint2*)(y + (size_t)s0 * FOUT + cbase));
            uint2 u1 = __ldg((const uint2*)(y + (size_t)s1 * FOUT + cbase));
            uint2 u2 = __ldg((const uint2*)(y + (size_t)s2 * FOUT + cbase));
            uint2 u3 = __ldg((const uint2*)(y + (size_t)s3 * FOUT + cbase));
            __half2 ax = __hadd2(__hadd2(bits2h(u0.x), bits2h(u1.x)),
                                 __hadd2(bits2h(u2.x), bits2h(u3.x)));
            __half2 ay = __hadd2(__hadd2(bits2h(u0.y), bits2h(u1.y)),
                                 __hadd2(bits2h(u2.y), bits2h(u3.y)));
            float2 f0 = __half22float2(ax);
            float2 f1 = __half22float2(ay);
            acc[0] += f0.x; acc[1] += f0.y; acc[2] += f1.x; acc[3] += f1.y;
        }
        for (; k < m; k++) {
            int ss = __shfl_sync(0xffffffffu, s, k);
            uint2 u = __ldg((const uint2*)(y + (size_t)ss * FOUT + cbase));
            float2 f0 = __half22float2(bits2h(u.x));
            float2 f1 = __half22float2(bits2h(u.y));
            acc[0] += f0.x; acc[1] += f0.y; acc[2] += f1.x; acc[3] += f1.y;
        }
    }
    float sc = __ldg(&inorm[n]);
    float4 bb = *(const float4*)(b2 + cbase);
    float4 o;
    o.x = acc[0] * sc + bb.x;
    o.y = acc[1] * sc + bb.y;
    o.z = acc[2] * sc + bb.z;
    o.w = acc[3] * sc + bb.w;
    *(float4*)(out + (size_t)n * FOUT + cbase) = o;
}

// ----------------------------- fp16 tensor GEMM (cp.async, BM=128 BN=128 BK=64)
#define ROWH 72
#define GEMM_SMEM ((2 * 128 * ROWH + 2 * 128 * ROWH) * 2)   // 72 KB

template<bool RELU, bool HAS_BIAS>
__global__ __launch_bounds__(256)
void gemm_f16_kernel(const __half* __restrict__ A, const __half* __restrict__ Bt,
                     __half* __restrict__ C,
                     const float* __restrict__ rowscale,
                     const float* __restrict__ bias,
                     int M, int N, int K) {
    constexpr int BK = 64;
    extern __shared__ __align__(16) __half dynsmem[];
    __half* As = dynsmem;
    __half* Bs = dynsmem + 2 * 128 * ROWH;

    const int tid  = threadIdx.x;
    const int warp = tid >> 5;
    const int lane = tid & 31;
    const int wm = warp & 3;
    const int wn = warp >> 2;
    const int quad = lane >> 3;
    const int qr   = lane & 7;

    const int brow0 = blockIdx.y * 128;
    const int bcol0 = blockIdx.x * 128;

    const int st_c8 = tid & 7;
    const int st_r  = tid >> 3;

    unsigned as_base = (unsigned)__cvta_generic_to_shared(As);
    unsigned bs_base = (unsigned)__cvta_generic_to_shared(Bs);

    unsigned a_off[2], b_off[4];
#pragma unroll
    for (int mt = 0; mt < 2; mt++) {
        int row = wm * 32 + mt * 16 + qr + (quad & 1) * 8;
        a_off[mt] = (unsigned)((row * ROWH + (quad >> 1) * 8) * 2);
    }
#pragma unroll
    for (int ntp = 0; ntp < 4; ntp++) {
        int row = wn * 64 + ntp * 16 + (quad >> 1) * 8 + qr;
        b_off[ntp] = (unsigned)((row * ROWH + (quad & 1) * 8) * 2);
    }

    float acc[2][8][4];
#pragma unroll
    for (int mt = 0; mt < 2; mt++)
#pragma unroll
        for (int nt = 0; nt < 8; nt++)
#pragma unroll
            for (int f = 0; f < 4; f++) acc[mt][nt][f] = 0.f;

    auto stage = [&](int k0, int buf) {
#pragma unroll
        for (int l = 0; l < 4; l++) {
            int row = st_r + l * 32;
            int grow = brow0 + row;
            unsigned dst = as_base + (unsigned)((buf * 128 * ROWH + row * ROWH + st_c8 * 8) * 2);
            const __half* src = A + (size_t)grow * K + k0 + st_c8 * 8;
            cp16(dst, src, (grow < M) ? 16 : 0);
        }
#pragma unroll
        for (int l = 0; l < 4; l++) {
            int row = st_r + l * 32;
            unsigned dst = bs_base + (unsigned)((buf * 128 * ROWH + row * ROWH + st_c8 * 8) * 2);
            const __half* src = Bt + (size_t)(bcol0 + row) * K + k0 + st_c8 * 8;
            cp16(dst, src, 16);
        }
        cp_commit();
    };

    stage(0, 0);
    int buf = 0;
    const int KT = K / BK;

    for (int kt = 0; kt < KT; kt++) {
        if (kt + 1 < KT) {
            stage((kt + 1) * BK, buf ^ 1);
            cp_wait<1>();
        } else {
            cp_wait<0>();
        }
        __syncthreads();

        unsigned abuf = as_base + (unsigned)(buf * 128 * ROWH * 2);
        unsigned bbuf = bs_base + (unsigned)(buf * 128 * ROWH * 2);
#pragma unroll
        for (int ks = 0; ks < 4; ks++) {
            unsigned a[2][4], b[4][4];
#pragma unroll
            for (int mt = 0; mt < 2; mt++)
                ldsm_x4(a[mt][0], a[mt][1], a[mt][2], a[mt][3],
                        abuf + a_off[mt] + ks * 32);
#pragma unroll
            for (int ntp = 0; ntp < 4; ntp++)
                ldsm_x4(b[ntp][0], b[ntp][1], b[ntp][2], b[ntp][3],
                        bbuf + b_off[ntp] + ks * 32);
#pragma unroll
            for (int mt = 0; mt < 2; mt++)
#pragma unroll
                for (int nt = 0; nt < 8; nt++) {
                    unsigned b0 = b[nt >> 1][(nt & 1) * 2 + 0];
                    unsigned b1 = b[nt >> 1][(nt & 1) * 2 + 1];
                    mma_f16(acc[mt][nt][0], acc[mt][nt][1],
                            acc[mt][nt][2], acc[mt][nt][3],
                            a[mt][0], a[mt][1], a[mt][2], a[mt][3], b0, b1);
                }
        }
        __syncthreads();
        buf ^= 1;
    }

    const int gid = lane >> 2;
    const int tig = lane & 3;
#pragma unroll
    for (int mt = 0; mt < 2; mt++) {
        int r0 = brow0 + wm * 32 + mt * 16 + gid;
        int r1 = r0 + 8;
        float rs0 = (r0 < M) ? __ldg(&rowscale[r0]) : 0.f;
        float rs1 = (r1 < M) ? __ldg(&rowscale[r1]) : 0.f;
#pragma unroll
        for (int nt = 0; nt < 8; nt++) {
            int c = bcol0 + wn * 64 + nt * 8 + 2 * tig;
            float2 bb = make_float2(0.f, 0.f);
            if (HAS_BIAS) bb = *(const float2*)(bias + c);
            float2 o0, o1;
            o0.x = acc[mt][nt][0] * rs0 + bb.x;
            o0.y = acc[mt][nt][1] * rs0 + bb.y;
            o1.x = acc[mt][nt][2] * rs1 + bb.x;
            o1.y = acc[mt][nt][3] * rs1 + bb.y;
            if (RELU) {
                o0.x = fmaxf(o0.x, 0.f); o0.y = fmaxf(o0.y, 0.f);
                o1.x = fmaxf(o1.x, 0.f); o1.y = fmaxf(o1.y, 0.f);
            }
            if (r0 < M) *(__half2*)(C + (size_t)r0 * N + c) = __floats2half2_rn(o0.x, o0.y);
            if (r1 < M) *(__half2*)(C + (size_t)r1 * N + c) = __floats2half2_rn(o1.x, o1.y);
        }
    }
}

// ----------------------------- launch ---------------------------------------
extern "C" void kernel_launch(void* const* d_in, const int* in_sizes, int n_in,
                              void* d_out, int out_size) {
    const float *features = nullptr, *W1 = nullptr, *b1 = nullptr,
                *W2 = nullptr, *b2 = nullptr;
    const int* ei = nullptr;
    for (int i = 0; i < n_in; i++) {
        switch (in_sizes[i]) {
            case NN * FIN:      features = (const float*)d_in[i]; break;
            case FIN * FHID:    W1 = (const float*)d_in[i]; break;
            case FHID:          b1 = (const float*)d_in[i]; break;
            case FHID * FOUT:   W2 = (const float*)d_in[i]; break;
            case FOUT:          b2 = (const float*)d_in[i]; break;
            case 2 * NE:        ei = (const int*)d_in[i]; break;
            default: break;
        }
    }
    float* out = (float*)d_out;

    float *onorm, *inorm;
    __half *agg1h, *x1h, *y_h, *feat_h, *w1t, *w2t;
    int *deg, *off, *cursor, *csr_src, *incl, *bsum;
    cudaGetSymbolAddress((void**)&agg1h,   g_agg1h);
    cudaGetSymbolAddress((void**)&x1h,     g_x1h);
    cudaGetSymbolAddress((void**)&y_h,     g_y_h);
    cudaGetSymbolAddress((void**)&feat_h,  g_feat_h);
    cudaGetSymbolAddress((void**)&w1t,     g_w1t);
    cudaGetSymbolAddress((void**)&w2t,     g_w2t);
    cudaGetSymbolAddress((void**)&onorm,   g_out_norm);
    cudaGetSymbolAddress((void**)&inorm,   g_in_norm);
    cudaGetSymbolAddress((void**)&deg,     g_deg);
    cudaGetSymbolAddress((void**)&off,     g_off);
    cudaGetSymbolAddress((void**)&cursor,  g_cursor);
    cudaGetSymbolAddress((void**)&csr_src, g_csr_src);
    cudaGetSymbolAddress((void**)&incl,    g_incl);
    cudaGetSymbolAddress((void**)&bsum,    g_bsum);

    cudaFuncSetAttribute(gemm_f16_kernel<true, true>,
                         cudaFuncAttributeMaxDynamicSharedMemorySize, GEMM_SMEM);
    cudaFuncSetAttribute(gemm_f16_kernel<false, false>,
                         cudaFuncAttributeMaxDynamicSharedMemorySize, GEMM_SMEM);

    const int T = 256;

    cudaMemsetAsync(deg, 0, 2 * NN * sizeof(int));
    // fused weight transpose + degree count
    {
        int deg_blocks = (NE / 4 + T - 1) / T;
        wtrans_degree_kernel<<<WT_BLOCKS + deg_blocks, T>>>(W1, w1t, W2, w2t, ei, deg);
    }
    scan1_kernel<<<NB, 256>>>(deg, incl, bsum);
    scan3_kernel<<<NB, 256>>>(deg, incl, bsum, off, cursor, onorm, inorm);
    scatter_f2h_kernel<<<(NE / 4 + T - 1) / T, T>>>(ei, cursor, csr_src,
                                                    features, onorm, feat_h);
    {
        long long threads = (long long)NN * 32;
        agg1_gather_kernel<<<(unsigned)((threads + T - 1) / T), T>>>(
            off, csr_src, feat_h, agg1h);
    }
    {
        dim3 grid(FHID / 128, (NN + 127) / 128);
        gemm_f16_kernel<true, true><<<grid, 256, GEMM_SMEM>>>(
            agg1h, w1t, x1h, inorm, b1, NN, FHID, FIN);
    }
    {
        dim3 grid(FOUT / 128, (NN + 127) / 128);
        gemm_f16_kernel<false, false><<<grid, 256, GEMM_SMEM>>>(
            x1h, w2t, y_h, onorm, nullptr, NN, FOUT, FHID);
    }
    {
        long long threads = (long long)NN * 64;   // 2 warps per node
        agg2_gather_kernel<<<(unsigned)((threads + T - 1) / T), T>>>(
            off, csr_src, y_h, inorm, b2, out);
    }
}

// round 16
// speedup vs baseline: 1.0789x; 1.0006x over previous
#include <cuda_runtime.h>
#include <cuda_fp16.h>
#include <cstdint>

#define NN   50000
#define NE   800000
#define FIN  128
#define FHID 384
#define FOUT 256
#define NB   196          // ceil(NN/256) scan blocks
#define F2H_BLOCKS 1024   // extra blocks in scan1 launch doing f2h

// ----------------------------- scratch --------------------------------------
__device__ __half g_agg1h[NN * FIN];             // 12.8 MB
__device__ __half g_x1h[(size_t)NN * FHID];      // 38.4 MB
__device__ __half g_y_h[(size_t)NN * FOUT];      // 25.6 MB
__device__ __half g_feat_h[NN * FIN];            // 12.8 MB (features * out_norm)
__device__ __half g_w1t[FHID * FIN];             // W1^T fp16 [384][128]
__device__ __half g_w2t[FOUT * FHID];            // W2^T fp16 [256][384]
__device__ int    g_deg[2 * NN];
__device__ float  g_out_norm[NN];
__device__ float  g_in_norm[NN];
__device__ int    g_off[NN + 1];
__device__ int    g_cursor[NN];
__device__ int    g_csr_src[NE];
__device__ int    g_incl[NN];
__device__ int    g_bsum[256];

// ----------------------------- helpers --------------------------------------
__device__ __forceinline__ void ldsm_x4(unsigned& r0, unsigned& r1,
                                        unsigned& r2, unsigned& r3, unsigned addr) {
    asm volatile("ldmatrix.sync.aligned.m8n8.x4.shared.b16 {%0,%1,%2,%3}, [%4];"
                 : "=r"(r0), "=r"(r1), "=r"(r2), "=r"(r3) : "r"(addr));
}

__device__ __forceinline__ void mma_f16(float& c0, float& c1, float& c2, float& c3,
                                        unsigned a0, unsigned a1, unsigned a2, unsigned a3,
                                        unsigned b0, unsigned b1) {
    asm volatile("mma.sync.aligned.m16n8k16.row.col.f32.f16.f16.f32 "
                 "{%0,%1,%2,%3}, {%4,%5,%6,%7}, {%8,%9}, {%0,%1,%2,%3};"
                 : "+f"(c0), "+f"(c1), "+f"(c2), "+f"(c3)
                 : "r"(a0), "r"(a1), "r"(a2), "r"(a3), "r"(b0), "r"(b1));
}

__device__ __forceinline__ void cp16(unsigned dst, const void* src, int src_sz) {
    asm volatile("cp.async.cg.shared.global [%0], [%1], 16, %2;"
                 :: "r"(dst), "l"(src), "r"(src_sz));
}
__device__ __forceinline__ void cp_commit() { asm volatile("cp.async.commit_group;"); }
template<int N_>
__device__ __forceinline__ void cp_wait() {
    asm volatile("cp.async.wait_group %0;" :: "n"(N_));
}
__device__ __forceinline__ __half2 bits2h(unsigned u) {
    return *reinterpret_cast<__half2*>(&u);
}

// ----------------------------- prelude kernels -------------------------------
// Fused: blocks 0-143 transpose W1/W2 to fp16; blocks 144+ count degrees.
#define WT_BLOCKS 144
__global__ void wtrans_degree_kernel(const float* __restrict__ W1, __half* __restrict__ W1t,
                                     const float* __restrict__ W2, __half* __restrict__ W2t,
                                     const int* __restrict__ ei, int* __restrict__ deg) {
    int b = blockIdx.x;
    if (b < WT_BLOCKS) {
        __shared__ float tile[32][33];
        const float* W; __half* Wt; int R, C, bx, by;
        if (b < 48) {         // W1: R=FIN, C=FHID; tiles 12 x 4
            W = W1; Wt = W1t; R = FIN; C = FHID;
            bx = (b % 12) * 32; by = (b / 12) * 32;
        } else {              // W2: R=FHID, C=FOUT; tiles 8 x 12
            int bb = b - 48;
            W = W2; Wt = W2t; R = FHID; C = FOUT;
            bx = (bb % 8) * 32; by = (bb / 8) * 32;
        }
        int tx = threadIdx.x & 31;
        int ty = threadIdx.x >> 5;
        int x = bx + tx;
#pragma unroll
        for (int i = 0; i < 32; i += 8) {
            int y = by + ty + i;
            if (y < R && x < C) tile[ty + i][tx] = W[(size_t)y * C + x];
        }
        __syncthreads();
        int k = by + tx;
#pragma unroll
        for (int i = 0; i < 32; i += 8) {
            int n = bx + ty + i;
            if (n < C && k < R)
                Wt[(size_t)n * R + k] = __float2half(tile[tx][ty + i]);
        }
    } else {
        int q = (b - WT_BLOCKS) * blockDim.x + threadIdx.x;
        if (q < NE / 4) {
            int4 s = ((const int4*)ei)[q];
            int4 d = ((const int4*)(ei + NE))[q];
            atomicAdd(&deg[s.x], 1); atomicAdd(&deg[s.y], 1);
            atomicAdd(&deg[s.z], 1); atomicAdd(&deg[s.w], 1);
            atomicAdd(&deg[NN + d.x], 1); atomicAdd(&deg[NN + d.y], 1);
            atomicAdd(&deg[NN + d.z], 1); atomicAdd(&deg[NN + d.w], 1);
        }
    }
}

// scan1 + f2h fused: blocks < NB do the per-block inclusive scan of deg_in;
// blocks >= NB convert features to fp16 pre-scaled by onorm (needs only deg).
__global__ void scan1_f2h_kernel(const int* __restrict__ deg,
                                 int* __restrict__ incl, int* __restrict__ bsum,
                                 const float* __restrict__ feat,
                                 __half* __restrict__ feat_h) {
    int b = blockIdx.x;
    if (b < NB) {
        __shared__ int sh[256];
        int t = threadIdx.x;
        int i = b * 256 + t;
        int v = (i < NN) ? deg[NN + i] : 0;
        sh[t] = v;
        __syncthreads();
#pragma unroll
        for (int d = 1; d < 256; d <<= 1) {
            int x = (t >= d) ? sh[t - d] : 0;
            __syncthreads();
            if (t >= d) sh[t] += x;
            __syncthreads();
        }
        if (i < NN) incl[i] = sh[t];
        if (t == 255) bsum[b] = sh[255];
    } else {
        const int n4 = NN * (FIN / 4);
        int idx0 = (b - NB) * 256 + threadIdx.x;
        for (int i = idx0; i < n4; i += F2H_BLOCKS * 256) {
            int row = i >> 5;
            float sc = rsqrtf((float)max(__ldg(&deg[row]), 1));
            float4 v = ((const float4*)feat)[i];
            __half2 h0 = __floats2half2_rn(v.x * sc, v.y * sc);
            __half2 h1 = __floats2half2_rn(v.z * sc, v.w * sc);
            ((uint2*)feat_h)[i] = make_uint2(*(unsigned*)&h0, *(unsigned*)&h1);
        }
    }
}

__global__ void scan3_kernel(const int* __restrict__ deg,
                             const int* __restrict__ incl, const int* __restrict__ bsum,
                             int* __restrict__ off, int* __restrict__ cursor,
                             float* __restrict__ onorm, float* __restrict__ inorm) {
    __shared__ int sh[256];
    int t = threadIdx.x;
    sh[t] = (t < blockIdx.x && t < NB) ? bsum[t] : 0;
    __syncthreads();
#pragma unroll
    for (int d = 128; d > 0; d >>= 1) {
        if (t < d) sh[t] += sh[t + d];
        __syncthreads();
    }
    int bpre = sh[0];
    int i = blockIdx.x * 256 + t;
    if (i < NN) {
        int din = deg[NN + i];
        int excl = bpre + incl[i] - din;
        off[i] = excl;
        cursor[i] = excl;
        onorm[i] = rsqrtf((float)max(deg[i], 1));
        inorm[i] = rsqrtf((float)max(din, 1));
    }
    if (i == 0) off[NN] = NE;
}

// Pure scatter, 1 edge per thread (max warps in flight for atomic latency).
__global__ void scatter_kernel(const int* __restrict__ ei,
                               int* __restrict__ cursor,
                               int* __restrict__ csr_src) {
    int e = blockIdx.x * blockDim.x + threadIdx.x;
    if (e < NE) {
        int src = ei[e];
        int dst = ei[NE + e];
        csr_src[atomicAdd(&cursor[dst], 1)] = src;
    }
}

// ----------------------------- gathers (MLP x4, proven) ----------------------
__global__ void agg1_gather_kernel(const int* __restrict__ off,
                                   const int* __restrict__ csr_src,
                                   const __half* __restrict__ feat,
                                   __half* __restrict__ aggh) {
    int n = (blockIdx.x * blockDim.x + threadIdx.x) >> 5;
    if (n >= NN) return;
    int lane = threadIdx.x & 31;
    int beg = off[n], end = off[n + 1];
    float4 acc = make_float4(0.f, 0.f, 0.f, 0.f);
    for (int j = beg; j < end; j += 32) {
        int m = min(32, end - j);
        int s = (lane < m) ? __ldg(&csr_src[j + lane]) : 0;
        int k = 0;
        for (; k + 4 <= m; k += 4) {
            int s0 = __shfl_sync(0xffffffffu, s, k + 0);
            int s1 = __shfl_sync(0xffffffffu, s, k + 1);
            int s2 = __shfl_sync(0xffffffffu, s, k + 2);
            int s3 = __shfl_sync(0xffffffffu, s, k + 3);
            uint2 u0 = __ldg((const uint2*)(feat + (size_t)s0 * FIN + lane * 4));
            uint2 u1 = __ldg((const uint2*)(feat + (size_t)s1 * FIN + lane * 4));
            uint2 u2 = __ldg((const uint2*)(feat + (size_t)s2 * FIN + lane * 4));
            uint2 u3 = __ldg((const uint2*)(feat + (size_t)s3 * FIN + lane * 4));
            __half2 ax = __hadd2(__hadd2(bits2h(u0.x), bits2h(u1.x)),
                                 __hadd2(bits2h(u2.x), bits2h(u3.x)));
            __half2 ay = __hadd2(__hadd2(bits2h(u0.y), bits2h(u1.y)),
                                 __hadd2(bits2h(u2.y), bits2h(u3.y)));
            float2 f0 = __half22float2(ax);
            float2 f1 = __half22float2(ay);
            acc.x += f0.x; acc.y += f0.y; acc.z += f1.x; acc.w += f1.y;
        }
        for (; k < m; k++) {
            int ss = __shfl_sync(0xffffffffu, s, k);
            uint2 u = __ldg((const uint2*)(feat + (size_t)ss * FIN + lane * 4));
            float2 a = __half22float2(bits2h(u.x));
            float2 b = __half22float2(bits2h(u.y));
            acc.x += a.x; acc.y += a.y; acc.z += b.x; acc.w += b.y;
        }
    }
    __half2 h0 = __floats2half2_rn(acc.x, acc.y);
    __half2 h1 = __floats2half2_rn(acc.z, acc.w);
    ((uint2*)(aggh + (size_t)n * FIN))[lane] = make_uint2(*(unsigned*)&h0, *(unsigned*)&h1);
}

// 2 warps per node: warp-half h owns columns [h*128, (h+1)*128), lane*4 halves.
__global__ void agg2_gather_kernel(const int* __restrict__ off,
                                   const int* __restrict__ csr_src,
                                   const __half* __restrict__ y,
                                   const float* __restrict__ inorm,
                                   const float* __restrict__ b2,
                                   float* __restrict__ out) {
    int gid = blockIdx.x * blockDim.x + threadIdx.x;
    int n = gid >> 6;
    if (n >= NN) return;
    int half = (gid >> 5) & 1;
    int lane = threadIdx.x & 31;
    int cbase = half * 128 + lane * 4;
    int beg = off[n], end = off[n + 1];
    float acc[4] = {0.f, 0.f, 0.f, 0.f};
    for (int j = beg; j < end; j += 32) {
        int m = min(32, end - j);
        int s = (lane < m) ? __ldg(&csr_src[j + lane]) : 0;
        int k = 0;
        for (; k + 4 <= m; k += 4) {
            int s0 = __shfl_sync(0xffffffffu, s, k + 0);
            int s1 = __shfl_sync(0xffffffffu, s, k + 1);
            int s2 = __shfl_sync(0xffffffffu, s, k + 2);
            int s3 = __shfl_sync(0xffffffffu, s, k + 3);
            uint2 u0 = __ldg((const uint2*)(y + (size_t)s0 * FOUT + cbase));
            uint2 u1 = __ldg((const uint2*)(y + (size_t)s1 * FOUT + cbase));
            uint2 u2 = __ldg((const uint2*)(y + (size_t)s2 * FOUT + cbase));
            uint2 u3 = __ldg((const uint2*)(y + (size_t)s3 * FOUT + cbase));
            __half2 ax = __hadd2(__hadd2(bits2h(u0.x), bits2h(u1.x)),
                                 __hadd2(bits2h(u2.x), bits2h(u3.x)));
            __half2 ay = __hadd2(__hadd2(bits2h(u0.y), bits2h(u1.y)),
                                 __hadd2(bits2h(u2.y), bits2h(u3.y)));
            float2 f0 = __half22float2(ax);
            float2 f1 = __half22float2(ay);
            acc[0] += f0.x; acc[1] += f0.y; acc[2] += f1.x; acc[3] += f1.y;
        }
        for (; k < m; k++) {
            int ss = __shfl_sync(0xffffffffu, s, k);
            uint2 u = __ldg((const uint2*)(y + (size_t)ss * FOUT + cbase));
            float2 f0 = __half22float2(bits2h(u.x));
            float2 f1 = __half22float2(bits2h(u.y));
            acc[0] += f0.x; acc[1] += f0.y; acc[2] += f1.x; acc[3] += f1.y;
        }
    }
    float sc = __ldg(&inorm[n]);
    float4 bb = *(const float4*)(b2 + cbase);
    float4 o;
    o.x = acc[0] * sc + bb.x;
    o.y = acc[1] * sc + bb.y;
    o.z = acc[2] * sc + bb.z;
    o.w = acc[3] * sc + bb.w;
    *(float4*)(out + (size_t)n * FOUT + cbase) = o;
}

// ----------------------------- fp16 tensor GEMM (cp.async, BM=128 BN=128 BK=64)
#define ROWH 72
#define GEMM_SMEM ((2 * 128 * ROWH + 2 * 128 * ROWH) * 2)   // 72 KB

template<bool RELU, bool HAS_BIAS>
__global__ __launch_bounds__(256)
void gemm_f16_kernel(const __half* __restrict__ A, const __half* __restrict__ Bt,
                     __half* __restrict__ C,
                     const float* __restrict__ rowscale,
                     const float* __restrict__ bias,
                     int M, int N, int K) {
    constexpr int BK = 64;
    extern __shared__ __align__(16) __half dynsmem[];
    __half* As = dynsmem;
    __half* Bs = dynsmem + 2 * 128 * ROWH;

    const int tid  = threadIdx.x;
    const int warp = tid >> 5;
    const int lane = tid & 31;
    const int wm = warp & 3;
    const int wn = warp >> 2;
    const int quad = lane >> 3;
    const int qr   = lane & 7;

    const int brow0 = blockIdx.y * 128;
    const int bcol0 = blockIdx.x * 128;

    const int st_c8 = tid & 7;
    const int st_r  = tid >> 3;

    unsigned as_base = (unsigned)__cvta_generic_to_shared(As);
    unsigned bs_base = (unsigned)__cvta_generic_to_shared(Bs);

    unsigned a_off[2], b_off[4];
#pragma unroll
    for (int mt = 0; mt < 2; mt++) {
        int row = wm * 32 + mt * 16 + qr + (quad & 1) * 8;
        a_off[mt] = (unsigned)((row * ROWH + (quad >> 1) * 8) * 2);
    }
#pragma unroll
    for (int ntp = 0; ntp < 4; ntp++) {
        int row = wn * 64 + ntp * 16 + (quad >> 1) * 8 + qr;
        b_off[ntp] = (unsigned)((row * ROWH + (quad & 1) * 8) * 2);
    }

    float acc[2][8][4];
#pragma unroll
    for (int mt = 0; mt < 2; mt++)
#pragma unroll
        for (int nt = 0; nt < 8; nt++)
#pragma unroll
            for (int f = 0; f < 4; f++) acc[mt][nt][f] = 0.f;

    auto stage = [&](int k0, int buf) {
#pragma unroll
        for (int l = 0; l < 4; l++) {
            int row = st_r + l * 32;
            int grow = brow0 + row;
            unsigned dst = as_base + (unsigned)((buf * 128 * ROWH + row * ROWH + st_c8 * 8) * 2);
            const __half* src = A + (size_t)grow * K + k0 + st_c8 * 8;
            cp16(dst, src, (grow < M) ? 16 : 0);
        }
#pragma unroll
        for (int l = 0; l < 4; l++) {
            int row = st_r + l * 32;
            unsigned dst = bs_base + (unsigned)((buf * 128 * ROWH + row * ROWH + st_c8 * 8) * 2);
            const __half* src = Bt + (size_t)(bcol0 + row) * K + k0 + st_c8 * 8;
            cp16(dst, src, 16);
        }
        cp_commit();
    };

    stage(0, 0);
    int buf = 0;
    const int KT = K / BK;

    for (int kt = 0; kt < KT; kt++) {
        if (kt + 1 < KT) {
            stage((kt + 1) * BK, buf ^ 1);
            cp_wait<1>();
        } else {
            cp_wait<0>();
        }
        __syncthreads();

        unsigned abuf = as_base + (unsigned)(buf * 128 * ROWH * 2);
        unsigned bbuf = bs_base + (unsigned)(buf * 128 * ROWH * 2);
#pragma unroll
        for (int ks = 0; ks < 4; ks++) {
            unsigned a[2][4], b[4][4];
#pragma unroll
            for (int mt = 0; mt < 2; mt++)
                ldsm_x4(a[mt][0], a[mt][1], a[mt][2], a[mt][3],
                        abuf + a_off[mt] + ks * 32);
#pragma unroll
            for (int ntp = 0; ntp < 4; ntp++)
                ldsm_x4(b[ntp][0], b[ntp][1], b[ntp][2], b[ntp][3],
                        bbuf + b_off[ntp] + ks * 32);
#pragma unroll
            for (int mt = 0; mt < 2; mt++)
#pragma unroll
                for (int nt = 0; nt < 8; nt++) {
                    unsigned b0 = b[nt >> 1][(nt & 1) * 2 + 0];
                    unsigned b1 = b[nt >> 1][(nt & 1) * 2 + 1];
                    mma_f16(acc[mt][nt][0], acc[mt][nt][1],
                            acc[mt][nt][2], acc[mt][nt][3],
                            a[mt][0], a[mt][1], a[mt][2], a[mt][3], b0, b1);
                }
        }
        __syncthreads();
        buf ^= 1;
    }

    const int gid = lane >> 2;
    const int tig = lane & 3;
#pragma unroll
    for (int mt = 0; mt < 2; mt++) {
        int r0 = brow0 + wm * 32 + mt * 16 + gid;
        int r1 = r0 + 8;
        float rs0 = (r0 < M) ? __ldg(&rowscale[r0]) : 0.f;
        float rs1 = (r1 < M) ? __ldg(&rowscale[r1]) : 0.f;
#pragma unroll
        for (int nt = 0; nt < 8; nt++) {
            int c = bcol0 + wn * 64 + nt * 8 + 2 * tig;
            float2 bb = make_float2(0.f, 0.f);
            if (HAS_BIAS) bb = *(const float2*)(bias + c);
            float2 o0, o1;
            o0.x = acc[mt][nt][0] * rs0 + bb.x;
            o0.y = acc[mt][nt][1] * rs0 + bb.y;
            o1.x = acc[mt][nt][2] * rs1 + bb.x;
            o1.y = acc[mt][nt][3] * rs1 + bb.y;
            if (RELU) {
                o0.x = fmaxf(o0.x, 0.f); o0.y = fmaxf(o0.y, 0.f);
                o1.x = fmaxf(o1.x, 0.f); o1.y = fmaxf(o1.y, 0.f);
            }
            if (r0 < M) *(__half2*)(C + (size_t)r0 * N + c) = __floats2half2_rn(o0.x, o0.y);
            if (r1 < M) *(__half2*)(C + (size_t)r1 * N + c) = __floats2half2_rn(o1.x, o1.y);
        }
    }
}

// ----------------------------- launch ---------------------------------------
extern "C" void kernel_launch(void* const* d_in, const int* in_sizes, int n_in,
                              void* d_out, int out_size) {
    const float *features = nullptr, *W1 = nullptr, *b1 = nullptr,
                *W2 = nullptr, *b2 = nullptr;
    const int* ei = nullptr;
    for (int i = 0; i < n_in; i++) {
        switch (in_sizes[i]) {
            case NN * FIN:      features = (const float*)d_in[i]; break;
            case FIN * FHID:    W1 = (const float*)d_in[i]; break;
            case FHID:          b1 = (const float*)d_in[i]; break;
            case FHID * FOUT:   W2 = (const float*)d_in[i]; break;
            case FOUT:          b2 = (const float*)d_in[i]; break;
            case 2 * NE:        ei = (const int*)d_in[i]; break;
            default: break;
        }
    }
    float* out = (float*)d_out;

    float *onorm, *inorm;
    __half *agg1h, *x1h, *y_h, *feat_h, *w1t, *w2t;
    int *deg, *off, *cursor, *csr_src, *incl, *bsum;
    cudaGetSymbolAddress((void**)&agg1h,   g_agg1h);
    cudaGetSymbolAddress((void**)&x1h,     g_x1h);
    cudaGetSymbolAddress((void**)&y_h,     g_y_h);
    cudaGetSymbolAddress((void**)&feat_h,  g_feat_h);
    cudaGetSymbolAddress((void**)&w1t,     g_w1t);
    cudaGetSymbolAddress((void**)&w2t,     g_w2t);
    cudaGetSymbolAddress((void**)&onorm,   g_out_norm);
    cudaGetSymbolAddress((void**)&inorm,   g_in_norm);
    cudaGetSymbolAddress((void**)&deg,     g_deg);
    cudaGetSymbolAddress((void**)&off,     g_off);
    cudaGetSymbolAddress((void**)&cursor,  g_cursor);
    cudaGetSymbolAddress((void**)&csr_src, g_csr_src);
    cudaGetSymbolAddress((void**)&incl,    g_incl);
    cudaGetSymbolAddress((void**)&bsum,    g_bsum);

    cudaFuncSetAttribute(gemm_f16_kernel<true, true>,
                         cudaFuncAttributeMaxDynamicSharedMemorySize, GEMM_SMEM);
    cudaFuncSetAttribute(gemm_f16_kernel<false, false>,
                         cudaFuncAttributeMaxDynamicSharedMemorySize, GEMM_SMEM);

    const int T = 256;

    cudaMemsetAsync(deg, 0, 2 * NN * sizeof(int));
    // fused weight transpose + degree count
    {
        int deg_blocks = (NE / 4 + T - 1) / T;
        wtrans_degree_kernel<<<WT_BLOCKS + deg_blocks, T>>>(W1, w1t, W2, w2t, ei, deg);
    }
    // fused scan phase 1 + fp16 feature conversion (f2h needs only deg)
    scan1_f2h_kernel<<<NB + F2H_BLOCKS, 256>>>(deg, incl, bsum, features, feat_h);
    scan3_kernel<<<NB, 256>>>(deg, incl, bsum, off, cursor, onorm, inorm);
    // pure scatter, 1 edge/thread
    scatter_kernel<<<(NE + T - 1) / T, T>>>(ei, cursor, csr_src);
    {
        long long threads = (long long)NN * 32;
        agg1_gather_kernel<<<(unsigned)((threads + T - 1) / T), T>>>(
            off, csr_src, feat_h, agg1h);
    }
    {
        dim3 grid(FHID / 128, (NN + 127) / 128);
        gemm_f16_kernel<true, true><<<grid, 256, GEMM_SMEM>>>(
            agg1h, w1t, x1h, inorm, b1, NN, FHID, FIN);
    }
    {
        dim3 grid(FOUT / 128, (NN + 127) / 128);
        gemm_f16_kernel<false, false><<<grid, 256, GEMM_SMEM>>>(
            x1h, w2t, y_h, onorm, nullptr, NN, FOUT, FHID);
    }
    {
        long long threads = (long long)NN * 64;   // 2 warps per node
        agg2_gather_kernel<<<(unsigned)((threads + T - 1) / T), T>>>(
            off, csr_src, y_h, inorm, b2, out);
    }
}

// round 17
// speedup vs baseline: 1.0877x; 1.0082x over previous
#include <cuda_runtime.h>
#include <cuda_fp16.h>
#include <cstdint>

#define NN   50000
#define NE   800000
#define FIN  128
#define FHID 384
#define FOUT 256
#define NB   196          // ceil(NN/256) scan blocks
#define F2H_BLOCKS 1024   // extra blocks in scan1 launch doing f2h

// ----------------------------- scratch --------------------------------------
__device__ __half g_agg1h[NN * FIN];             // 12.8 MB
__device__ __half g_x1h[(size_t)NN * FHID];      // 38.4 MB
__device__ __half g_y_h[(size_t)NN * FOUT];      // 25.6 MB
__device__ __half g_feat_h[NN * FIN];            // 12.8 MB (features * out_norm)
__device__ __half g_w1t[FHID * FIN];             // W1^T fp16 [384][128]
__device__ __half g_w2t[FOUT * FHID];            // W2^T fp16 [256][384]
__device__ int    g_deg[2 * NN];
__device__ float  g_out_norm[NN];
__device__ float  g_in_norm[NN];
__device__ int    g_off[NN + 1];
__device__ int    g_csr_src[NE];
__device__ int    g_rank[NE];                    // per-edge rank within its dst bucket
__device__ int    g_incl[NN];
__device__ int    g_bsum[256];

// ----------------------------- helpers --------------------------------------
__device__ __forceinline__ void ldsm_x4(unsigned& r0, unsigned& r1,
                                        unsigned& r2, unsigned& r3, unsigned addr) {
    asm volatile("ldmatrix.sync.aligned.m8n8.x4.shared.b16 {%0,%1,%2,%3}, [%4];"
                 : "=r"(r0), "=r"(r1), "=r"(r2), "=r"(r3) : "r"(addr));
}

__device__ __forceinline__ void mma_f16(float& c0, float& c1, float& c2, float& c3,
                                        unsigned a0, unsigned a1, unsigned a2, unsigned a3,
                                        unsigned b0, unsigned b1) {
    asm volatile("mma.sync.aligned.m16n8k16.row.col.f32.f16.f16.f32 "
                 "{%0,%1,%2,%3}, {%4,%5,%6,%7}, {%8,%9}, {%0,%1,%2,%3};"
                 : "+f"(c0), "+f"(c1), "+f"(c2), "+f"(c3)
                 : "r"(a0), "r"(a1), "r"(a2), "r"(a3), "r"(b0), "r"(b1));
}

__device__ __forceinline__ void cp16(unsigned dst, const void* src, int src_sz) {
    asm volatile("cp.async.cg.shared.global [%0], [%1], 16, %2;"
                 :: "r"(dst), "l"(src), "r"(src_sz));
}
__device__ __forceinline__ void cp_commit() { asm volatile("cp.async.commit_group;"); }
template<int N_>
__device__ __forceinline__ void cp_wait() {
    asm volatile("cp.async.wait_group %0;" :: "n"(N_));
}
__device__ __forceinline__ __half2 bits2h(unsigned u) {
    return *reinterpret_cast<__half2*>(&u);
}

// ----------------------------- prelude kernels -------------------------------
// Fused: blocks 0-143 transpose W1/W2 to fp16; blocks 144+ count degrees AND
// record each edge's rank within its dst bucket (returned atomic value).
#define WT_BLOCKS 144
__global__ void wtrans_degree_kernel(const float* __restrict__ W1, __half* __restrict__ W1t,
                                     const float* __restrict__ W2, __half* __restrict__ W2t,
                                     const int* __restrict__ ei, int* __restrict__ deg,
                                     int* __restrict__ rank) {
    int b = blockIdx.x;
    if (b < WT_BLOCKS) {
        __shared__ float tile[32][33];
        const float* W; __half* Wt; int R, C, bx, by;
        if (b < 48) {         // W1: R=FIN, C=FHID; tiles 12 x 4
            W = W1; Wt = W1t; R = FIN; C = FHID;
            bx = (b % 12) * 32; by = (b / 12) * 32;
        } else {              // W2: R=FHID, C=FOUT; tiles 8 x 12
            int bb = b - 48;
            W = W2; Wt = W2t; R = FHID; C = FOUT;
            bx = (bb % 8) * 32; by = (bb / 8) * 32;
        }
        int tx = threadIdx.x & 31;
        int ty = threadIdx.x >> 5;
        int x = bx + tx;
#pragma unroll
        for (int i = 0; i < 32; i += 8) {
            int y = by + ty + i;
            if (y < R && x < C) tile[ty + i][tx] = W[(size_t)y * C + x];
        }
        __syncthreads();
        int k = by + tx;
#pragma unroll
        for (int i = 0; i < 32; i += 8) {
            int n = bx + ty + i;
            if (n < C && k < R)
                Wt[(size_t)n * R + k] = __float2half(tile[tx][ty + i]);
        }
    } else {
        int q = (b - WT_BLOCKS) * blockDim.x + threadIdx.x;
        if (q < NE / 4) {
            int4 s = ((const int4*)ei)[q];
            int4 d = ((const int4*)(ei + NE))[q];
            atomicAdd(&deg[s.x], 1); atomicAdd(&deg[s.y], 1);
            atomicAdd(&deg[s.z], 1); atomicAdd(&deg[s.w], 1);
            int4 r;
            r.x = atomicAdd(&deg[NN + d.x], 1);
            r.y = atomicAdd(&deg[NN + d.y], 1);
            r.z = atomicAdd(&deg[NN + d.z], 1);
            r.w = atomicAdd(&deg[NN + d.w], 1);
            ((int4*)rank)[q] = r;     // coalesced store; no random dependency
        }
    }
}

// scan1 + f2h fused: blocks < NB do the per-block inclusive scan of deg_in;
// blocks >= NB convert features to fp16 pre-scaled by onorm (needs only deg).
__global__ void scan1_f2h_kernel(const int* __restrict__ deg,
                                 int* __restrict__ incl, int* __restrict__ bsum,
                                 const float* __restrict__ feat,
                                 __half* __restrict__ feat_h) {
    int b = blockIdx.x;
    if (b < NB) {
        __shared__ int sh[256];
        int t = threadIdx.x;
        int i = b * 256 + t;
        int v = (i < NN) ? deg[NN + i] : 0;
        sh[t] = v;
        __syncthreads();
#pragma unroll
        for (int d = 1; d < 256; d <<= 1) {
            int x = (t >= d) ? sh[t - d] : 0;
            __syncthreads();
            if (t >= d) sh[t] += x;
            __syncthreads();
        }
        if (i < NN) incl[i] = sh[t];
        if (t == 255) bsum[b] = sh[255];
    } else {
        const int n4 = NN * (FIN / 4);
        int idx0 = (b - NB) * 256 + threadIdx.x;
        for (int i = idx0; i < n4; i += F2H_BLOCKS * 256) {
            int row = i >> 5;
            float sc = rsqrtf((float)max(__ldg(&deg[row]), 1));
            float4 v = ((const float4*)feat)[i];
            __half2 h0 = __floats2half2_rn(v.x * sc, v.y * sc);
            __half2 h1 = __floats2half2_rn(v.z * sc, v.w * sc);
            ((uint2*)feat_h)[i] = make_uint2(*(unsigned*)&h0, *(unsigned*)&h1);
        }
    }
}

__global__ void scan3_kernel(const int* __restrict__ deg,
                             const int* __restrict__ incl, const int* __restrict__ bsum,
                             int* __restrict__ off,
                             float* __restrict__ onorm, float* __restrict__ inorm) {
    __shared__ int sh[256];
    int t = threadIdx.x;
    sh[t] = (t < blockIdx.x && t < NB) ? bsum[t] : 0;
    __syncthreads();
#pragma unroll
    for (int d = 128; d > 0; d >>= 1) {
        if (t < d) sh[t] += sh[t + d];
        __syncthreads();
    }
    int bpre = sh[0];
    int i = blockIdx.x * 256 + t;
    if (i < NN) {
        int din = deg[NN + i];
        int excl = bpre + incl[i] - din;
        off[i] = excl;
        onorm[i] = rsqrtf((float)max(deg[i], 1));
        inorm[i] = rsqrtf((float)max(din, 1));
    }
    if (i == 0) off[NN] = NE;
}

// Atomic-free scatter: position = off[dst] + rank[e] (rank from degree pass).
__global__ void scatter_kernel(const int* __restrict__ ei,
                               const int* __restrict__ rank,
                               const int* __restrict__ off,
                               int* __restrict__ csr_src) {
    int q = blockIdx.x * blockDim.x + threadIdx.x;
    if (q < NE / 4) {
        int4 s = ((const int4*)ei)[q];
        int4 d = ((const int4*)(ei + NE))[q];
        int4 r = ((const int4*)rank)[q];
        csr_src[__ldg(&off[d.x]) + r.x] = s.x;
        csr_src[__ldg(&off[d.y]) + r.y] = s.y;
        csr_src[__ldg(&off[d.z]) + r.z] = s.z;
        csr_src[__ldg(&off[d.w]) + r.w] = s.w;
    }
}

// ----------------------------- gathers (MLP x4, proven) ----------------------
__global__ void agg1_gather_kernel(const int* __restrict__ off,
                                   const int* __restrict__ csr_src,
                                   const __half* __restrict__ feat,
                                   __half* __restrict__ aggh) {
    int n = (blockIdx.x * blockDim.x + threadIdx.x) >> 5;
    if (n >= NN) return;
    int lane = threadIdx.x & 31;
    int beg = off[n], end = off[n + 1];
    float4 acc = make_float4(0.f, 0.f, 0.f, 0.f);
    for (int j = beg; j < end; j += 32) {
        int m = min(32, end - j);
        int s = (lane < m) ? __ldg(&csr_src[j + lane]) : 0;
        int k = 0;
        for (; k + 4 <= m; k += 4) {
            int s0 = __shfl_sync(0xffffffffu, s, k + 0);
            int s1 = __shfl_sync(0xffffffffu, s, k + 1);
            int s2 = __shfl_sync(0xffffffffu, s, k + 2);
            int s3 = __shfl_sync(0xffffffffu, s, k + 3);
            uint2 u0 = __ldg((const uint2*)(feat + (size_t)s0 * FIN + lane * 4));
            uint2 u1 = __ldg((const uint2*)(feat + (size_t)s1 * FIN + lane * 4));
            uint2 u2 = __ldg((const uint2*)(feat + (size_t)s2 * FIN + lane * 4));
            uint2 u3 = __ldg((const uint2*)(feat + (size_t)s3 * FIN + lane * 4));
            __half2 ax = __hadd2(__hadd2(bits2h(u0.x), bits2h(u1.x)),
                                 __hadd2(bits2h(u2.x), bits2h(u3.x)));
            __half2 ay = __hadd2(__hadd2(bits2h(u0.y), bits2h(u1.y)),
                                 __hadd2(bits2h(u2.y), bits2h(u3.y)));
            float2 f0 = __half22float2(ax);
            float2 f1 = __half22float2(ay);
            acc.x += f0.x; acc.y += f0.y; acc.z += f1.x; acc.w += f1.y;
        }
        for (; k < m; k++) {
            int ss = __shfl_sync(0xffffffffu, s, k);
            uint2 u = __ldg((const uint2*)(feat + (size_t)ss * FIN + lane * 4));
            float2 a = __half22float2(bits2h(u.x));
            float2 b = __half22float2(bits2h(u.y));
            acc.x += a.x; acc.y += a.y; acc.z += b.x; acc.w += b.y;
        }
    }
    __half2 h0 = __floats2half2_rn(acc.x, acc.y);
    __half2 h1 = __floats2half2_rn(acc.z, acc.w);
    ((uint2*)(aggh + (size_t)n * FIN))[lane] = make_uint2(*(unsigned*)&h0, *(unsigned*)&h1);
}

// 2 warps per node: warp-half h owns columns [h*128, (h+1)*128), lane*4 halves.
__global__ void agg2_gather_kernel(const int* __restrict__ off,
                                   const int* __restrict__ csr_src,
                                   const __half* __restrict__ y,
                                   const float* __restrict__ inorm,
                                   const float* __restrict__ b2,
                                   float* __restrict__ out) {
    int gid = blockIdx.x * blockDim.x + threadIdx.x;
    int n = gid >> 6;
    if (n >= NN) return;
    int half = (gid >> 5) & 1;
    int lane = threadIdx.x & 31;
    int cbase = half * 128 + lane * 4;
    int beg = off[n], end = off[n + 1];
    float acc[4] = {0.f, 0.f, 0.f, 0.f};
    for (int j = beg; j < end; j += 32) {
        int m = min(32, end - j);
        int s = (lane < m) ? __ldg(&csr_src[j + lane]) : 0;
        int k = 0;
        for (; k + 4 <= m; k += 4) {
            int s0 = __shfl_sync(0xffffffffu, s, k + 0);
            int s1 = __shfl_sync(0xffffffffu, s, k + 1);
            int s2 = __shfl_sync(0xffffffffu, s, k + 2);
            int s3 = __shfl_sync(0xffffffffu, s, k + 3);
            uint2 u0 = __ldg((const uint2*)(y + (size_t)s0 * FOUT + cbase));
            uint2 u1 = __ldg((const uint2*)(y + (size_t)s1 * FOUT + cbase));
            uint2 u2 = __ldg((const uint2*)(y + (size_t)s2 * FOUT + cbase));
            uint2 u3 = __ldg((const uint2*)(y + (size_t)s3 * FOUT + cbase));
            __half2 ax = __hadd2(__hadd2(bits2h(u0.x), bits2h(u1.x)),
                                 __hadd2(bits2h(u2.x), bits2h(u3.x)));
            __half2 ay = __hadd2(__hadd2(bits2h(u0.y), bits2h(u1.y)),
                                 __hadd2(bits2h(u2.y), bits2h(u3.y)));
            float2 f0 = __half22float2(ax);
            float2 f1 = __half22float2(ay);
            acc[0] += f0.x; acc[1] += f0.y; acc[2] += f1.x; acc[3] += f1.y;
        }
        for (; k < m; k++) {
            int ss = __shfl_sync(0xffffffffu, s, k);
            uint2 u = __ldg((const uint2*)(y + (size_t)ss * FOUT + cbase));
            float2 f0 = __half22float2(bits2h(u.x));
            float2 f1 = __half22float2(bits2h(u.y));
            acc[0] += f0.x; acc[1] += f0.y; acc[2] += f1.x; acc[3] += f1.y;
        }
    }
    float sc = __ldg(&inorm[n]);
    float4 bb = *(const float4*)(b2 + cbase);
    float4 o;
    o.x = acc[0] * sc + bb.x;
    o.y = acc[1] * sc + bb.y;
    o.z = acc[2] * sc + bb.z;
    o.w = acc[3] * sc + bb.w;
    *(float4*)(out + (size_t)n * FOUT + cbase) = o;
}

// ----------------------------- fp16 tensor GEMM (cp.async, BM=128 BN=128 BK=64)
#define ROWH 72
#define GEMM_SMEM ((2 * 128 * ROWH + 2 * 128 * ROWH) * 2)   // 72 KB

template<bool RELU, bool HAS_BIAS>
__global__ __launch_bounds__(256)
void gemm_f16_kernel(const __half* __restrict__ A, const __half* __restrict__ Bt,
                     __half* __restrict__ C,
                     const float* __restrict__ rowscale,
                     const float* __restrict__ bias,
                     int M, int N, int K) {
    constexpr int BK = 64;
    extern __shared__ __align__(16) __half dynsmem[];
    __half* As = dynsmem;
    __half* Bs = dynsmem + 2 * 128 * ROWH;

    const int tid  = threadIdx.x;
    const int warp = tid >> 5;
    const int lane = tid & 31;
    const int wm = warp & 3;
    const int wn = warp >> 2;
    const int quad = lane >> 3;
    const int qr   = lane & 7;

    const int brow0 = blockIdx.y * 128;
    const int bcol0 = blockIdx.x * 128;

    const int st_c8 = tid & 7;
    const int st_r  = tid >> 3;

    unsigned as_base = (unsigned)__cvta_generic_to_shared(As);
    unsigned bs_base = (unsigned)__cvta_generic_to_shared(Bs);

    unsigned a_off[2], b_off[4];
#pragma unroll
    for (int mt = 0; mt < 2; mt++) {
        int row = wm * 32 + mt * 16 + qr + (quad & 1) * 8;
        a_off[mt] = (unsigned)((row * ROWH + (quad >> 1) * 8) * 2);
    }
#pragma unroll
    for (int ntp = 0; ntp < 4; ntp++) {
        int row = wn * 64 + ntp * 16 + (quad >> 1) * 8 + qr;
        b_off[ntp] = (unsigned)((row * ROWH + (quad & 1) * 8) * 2);
    }

    float acc[2][8][4];
#pragma unroll
    for (int mt = 0; mt < 2; mt++)
#pragma unroll
        for (int nt = 0; nt < 8; nt++)
#pragma unroll
            for (int f = 0; f < 4; f++) acc[mt][nt][f] = 0.f;

    auto stage = [&](int k0, int buf) {
#pragma unroll
        for (int l = 0; l < 4; l++) {
            int row = st_r + l * 32;
            int grow = brow0 + row;
            unsigned dst = as_base + (unsigned)((buf * 128 * ROWH + row * ROWH + st_c8 * 8) * 2);
            const __half* src = A + (size_t)grow * K + k0 + st_c8 * 8;
            cp16(dst, src, (grow < M) ? 16 : 0);
        }
#pragma unroll
        for (int l = 0; l < 4; l++) {
            int row = st_r + l * 32;
            unsigned dst = bs_base + (unsigned)((buf * 128 * ROWH + row * ROWH + st_c8 * 8) * 2);
            const __half* src = Bt + (size_t)(bcol0 + row) * K + k0 + st_c8 * 8;
            cp16(dst, src, 16);
        }
        cp_commit();
    };

    stage(0, 0);
    int buf = 0;
    const int KT = K / BK;

    for (int kt = 0; kt < KT; kt++) {
        if (kt + 1 < KT) {
            stage((kt + 1) * BK, buf ^ 1);
            cp_wait<1>();
        } else {
            cp_wait<0>();
        }
        __syncthreads();

        unsigned abuf = as_base + (unsigned)(buf * 128 * ROWH * 2);
        unsigned bbuf = bs_base + (unsigned)(buf * 128 * ROWH * 2);
#pragma unroll
        for (int ks = 0; ks < 4; ks++) {
            unsigned a[2][4], b[4][4];
#pragma unroll
            for (int mt = 0; mt < 2; mt++)
                ldsm_x4(a[mt][0], a[mt][1], a[mt][2], a[mt][3],
                        abuf + a_off[mt] + ks * 32);
#pragma unroll
            for (int ntp = 0; ntp < 4; ntp++)
                ldsm_x4(b[ntp][0], b[ntp][1], b[ntp][2], b[ntp][3],
                        bbuf + b_off[ntp] + ks * 32);
#pragma unroll
            for (int mt = 0; mt < 2; mt++)
#pragma unroll
                for (int nt = 0; nt < 8; nt++) {
                    unsigned b0 = b[nt >> 1][(nt & 1) * 2 + 0];
                    unsigned b1 = b[nt >> 1][(nt & 1) * 2 + 1];
                    mma_f16(acc[mt][nt][0], acc[mt][nt][1],
                            acc[mt][nt][2], acc[mt][nt][3],
                            a[mt][0], a[mt][1], a[mt][2], a[mt][3], b0, b1);
                }
        }
        __syncthreads();
        buf ^= 1;
    }

    const int gid = lane >> 2;
    const int tig = lane & 3;
#pragma unroll
    for (int mt = 0; mt < 2; mt++) {
        int r0 = brow0 + wm * 32 + mt * 16 + gid;
        int r1 = r0 + 8;
        float rs0 = (r0 < M) ? __ldg(&rowscale[r0]) : 0.f;
        float rs1 = (r1 < M) ? __ldg(&rowscale[r1]) : 0.f;
#pragma unroll
        for (int nt = 0; nt < 8; nt++) {
            int c = bcol0 + wn * 64 + nt * 8 + 2 * tig;
            float2 bb = make_float2(0.f, 0.f);
            if (HAS_BIAS) bb = *(const float2*)(bias + c);
            float2 o0, o1;
            o0.x = acc[mt][nt][0] * rs0 + bb.x;
            o0.y = acc[mt][nt][1] * rs0 + bb.y;
            o1.x = acc[mt][nt][2] * rs1 + bb.x;
            o1.y = acc[mt][nt][3] * rs1 + bb.y;
            if (RELU) {
                o0.x = fmaxf(o0.x, 0.f); o0.y = fmaxf(o0.y, 0.f);
                o1.x = fmaxf(o1.x, 0.f); o1.y = fmaxf(o1.y, 0.f);
            }
            if (r0 < M) *(__half2*)(C + (size_t)r0 * N + c) = __floats2half2_rn(o0.x, o0.y);
            if (r1 < M) *(__half2*)(C + (size_t)r1 * N + c) = __floats2half2_rn(o1.x, o1.y);
        }
    }
}

// ----------------------------- launch ---------------------------------------
extern "C" void kernel_launch(void* const* d_in, const int* in_sizes, int n_in,
                              void* d_out, int out_size) {
    const float *features = nullptr, *W1 = nullptr, *b1 = nullptr,
                *W2 = nullptr, *b2 = nullptr;
    const int* ei = nullptr;
    for (int i = 0; i < n_in; i++) {
        switch (in_sizes[i]) {
            case NN * FIN:      features = (const float*)d_in[i]; break;
            case FIN * FHID:    W1 = (const float*)d_in[i]; break;
            case FHID:          b1 = (const float*)d_in[i]; break;
            case FHID * FOUT:   W2 = (const float*)d_in[i]; break;
            case FOUT:          b2 = (const float*)d_in[i]; break;
            case 2 * NE:        ei = (const int*)d_in[i]; break;
            default: break;
        }
    }
    float* out = (float*)d_out;

    float *onorm, *inorm;
    __half *agg1h, *x1h, *y_h, *feat_h, *w1t, *w2t;
    int *deg, *off, *csr_src, *rank, *incl, *bsum;
    cudaGetSymbolAddress((void**)&agg1h,   g_agg1h);
    cudaGetSymbolAddress((void**)&x1h,     g_x1h);
    cudaGetSymbolAddress((void**)&y_h,     g_y_h);
    cudaGetSymbolAddress((void**)&feat_h,  g_feat_h);
    cudaGetSymbolAddress((void**)&w1t,     g_w1t);
    cudaGetSymbolAddress((void**)&w2t,     g_w2t);
    cudaGetSymbolAddress((void**)&onorm,   g_out_norm);
    cudaGetSymbolAddress((void**)&inorm,   g_in_norm);
    cudaGetSymbolAddress((void**)&deg,     g_deg);
    cudaGetSymbolAddress((void**)&off,     g_off);
    cudaGetSymbolAddress((void**)&csr_src, g_csr_src);
    cudaGetSymbolAddress((void**)&rank,    g_rank);
    cudaGetSymbolAddress((void**)&incl,    g_incl);
    cudaGetSymbolAddress((void**)&bsum,    g_bsum);

    cudaFuncSetAttribute(gemm_f16_kernel<true, true>,
                         cudaFuncAttributeMaxDynamicSharedMemorySize, GEMM_SMEM);
    cudaFuncSetAttribute(gemm_f16_kernel<false, false>,
                         cudaFuncAttributeMaxDynamicSharedMemorySize, GEMM_SMEM);

    const int T = 256;

    cudaMemsetAsync(deg, 0, 2 * NN * sizeof(int));
    // fused weight transpose + degree count + edge ranks
    {
        int deg_blocks = (NE / 4 + T - 1) / T;
        wtrans_degree_kernel<<<WT_BLOCKS + deg_blocks, T>>>(W1, w1t, W2, w2t,
                                                            ei, deg, rank);
    }
    // fused scan phase 1 + fp16 feature conversion
    scan1_f2h_kernel<<<NB + F2H_BLOCKS, 256>>>(deg, incl, bsum, features, feat_h);
    scan3_kernel<<<NB, 256>>>(deg, incl, bsum, off, onorm, inorm);
    // atomic-free scatter via precomputed ranks
    scatter_kernel<<<(NE / 4 + T - 1) / T, T>>>(ei, rank, off, csr_src);
    {
        long long threads = (long long)NN * 32;
        agg1_gather_kernel<<<(unsigned)((threads + T - 1) / T), T>>>(
            off, csr_src, feat_h, agg1h);
    }
    {
        dim3 grid(FHID / 128, (NN + 127) / 128);
        gemm_f16_kernel<true, true><<<grid, 256, GEMM_SMEM>>>(
            agg1h, w1t, x1h, inorm, b1, NN, FHID, FIN);
    }
    {
        dim3 grid(FOUT / 128, (NN + 127) / 128);
        gemm_f16_kernel<false, false><<<grid, 256, GEMM_SMEM>>>(
            x1h, w2t, y_h, onorm, nullptr, NN, FOUT, FHID);
    }
    {
        long long threads = (long long)NN * 64;   // 2 warps per node
        agg2_gather_kernel<<<(unsigned)((threads + T - 1) / T), T>>>(
            off, csr_src, y_h, inorm, b2, out);
    }
}